// round 1
// baseline (speedup 1.0000x reference)
#include <cuda_runtime.h>
#include <cuda_bf16.h>
#include <cstdint>

// Problem constants
#define NN 100000
#define EE 1600000
#define RR 12
#define F_IN 16
#define HID 128
#define OUTD 64
#define PP 4096
#define CMAX ((RR + 1) * HID)  // 1664

// ---------------- scratch (device globals; no allocation allowed) -------------
__device__ float    g_T[(size_t)NN * CMAX];      // per-relation transformed feats [N, (R+1)*dout]
__device__ float    g_HA[(size_t)NN * HID];
__device__ float    g_HB[(size_t)NN * HID];
__device__ float    g_Bw[HID * CMAX];            // concatenated weights for current layer
__device__ int      g_deg[NN + 1];
__device__ int      g_off[NN + 1];
__device__ int      g_cur[NN];
__device__ unsigned g_csr[EE];                   // packed src | (etype << 20)
__device__ float    g_hf[NN * 2];

// ---------------- CSR build ---------------------------------------------------
__global__ void zeroDegKernel() {
    int i = blockIdx.x * blockDim.x + threadIdx.x;
    if (i <= NN) g_deg[i] = 0;
}

__global__ void histKernel(const int* __restrict__ dst) {
    int e = blockIdx.x * blockDim.x + threadIdx.x;
    if (e < EE) atomicAdd(&g_deg[dst[e]], 1);
}

__global__ void scanKernel() {
    __shared__ int sh[1024];
    __shared__ int carry;
    int t = threadIdx.x;
    if (t == 0) carry = 0;
    __syncthreads();
    for (int base = 0; base < NN; base += 1024) {
        int i = base + t;
        int v = (i < NN) ? g_deg[i] : 0;
        sh[t] = v;
        __syncthreads();
        for (int s = 1; s < 1024; s <<= 1) {
            int tmp = (t >= s) ? sh[t - s] : 0;
            __syncthreads();
            sh[t] += tmp;
            __syncthreads();
        }
        int excl = sh[t] - v;
        if (i < NN) g_off[i] = carry + excl;
        int total = sh[1023];
        __syncthreads();
        if (t == 0) carry += total;
        __syncthreads();
    }
    if (t == 0) g_off[NN] = carry;
}

__global__ void copyCurKernel() {
    int i = blockIdx.x * blockDim.x + threadIdx.x;
    if (i < NN) g_cur[i] = g_off[i];
}

__global__ void scatterKernel(const int* __restrict__ src, const int* __restrict__ dst,
                              const int* __restrict__ et) {
    int e = blockIdx.x * blockDim.x + threadIdx.x;
    if (e >= EE) return;
    int d = dst[e];
    int pos = atomicAdd(&g_cur[d], 1);
    g_csr[pos] = (unsigned)src[e] | ((unsigned)et[e] << 20);
}

// ---------------- weight concatenation: Bw[i][r*dout+o] = W[r][i][o]; r==R -> L
__global__ void buildBwKernel(const float* __restrict__ W, const float* __restrict__ L,
                              int din, int dout) {
    int C = (RR + 1) * dout;
    int total = din * C;
    int idx = blockIdx.x * blockDim.x + threadIdx.x;
    if (idx >= total) return;
    int i = idx / C;
    int c = idx % C;
    int r = c / dout;
    int o = c % dout;
    g_Bw[idx] = (r < RR) ? W[((size_t)r * din + i) * dout + o] : L[(size_t)i * dout + o];
}

// ---------------- fp32 tiled GEMM: T = Hin[M,K] @ Bw[K,C] --------------------
#define TM 128
#define TN 128
#define TK 16
__global__ void gemmKernel(const float* __restrict__ A, int M, int K, int C) {
    __shared__ float As[TK][TM];
    __shared__ float Bs[TK][TN];
    int tid = threadIdx.x;          // 256
    int tx = tid & 15, ty = tid >> 4;
    int row0 = blockIdx.y * TM, col0 = blockIdx.x * TN;
    float acc[8][8];
#pragma unroll
    for (int i = 0; i < 8; i++)
#pragma unroll
        for (int j = 0; j < 8; j++) acc[i][j] = 0.f;

    for (int kt = 0; kt < K; kt += TK) {
        for (int e = tid; e < TM * TK; e += 256) {
            int r = e / TK, k = e % TK;
            int gr = row0 + r;
            As[k][r] = (gr < M) ? A[(size_t)gr * K + kt + k] : 0.f;
        }
        for (int e = tid; e < TK * TN; e += 256) {
            int k = e / TN, c = e % TN;
            int gc = col0 + c;
            Bs[k][c] = (gc < C) ? g_Bw[(size_t)(kt + k) * C + gc] : 0.f;
        }
        __syncthreads();
#pragma unroll
        for (int k = 0; k < TK; k++) {
            float a[8], b[8];
#pragma unroll
            for (int i = 0; i < 8; i++) a[i] = As[k][ty + 16 * i];
#pragma unroll
            for (int j = 0; j < 8; j++) b[j] = Bs[k][tx + 16 * j];
#pragma unroll
            for (int i = 0; i < 8; i++)
#pragma unroll
                for (int j = 0; j < 8; j++) acc[i][j] += a[i] * b[j];
        }
        __syncthreads();
    }
#pragma unroll
    for (int i = 0; i < 8; i++) {
        int gr = row0 + ty + 16 * i;
        if (gr >= M) continue;
#pragma unroll
        for (int j = 0; j < 8; j++) {
            int gc = col0 + tx + 16 * j;
            if (gc < C) g_T[(size_t)gr * C + gc] = acc[i][j];
        }
    }
}

// ---------------- aggregation: warp per node, gather incoming rows of g_T -----
template <int DOUT>
__global__ void aggKernel(const float* __restrict__ bias, float* __restrict__ Hout) {
    const int C = (RR + 1) * DOUT;
    int warp = (blockIdx.x * blockDim.x + threadIdx.x) >> 5;
    int lane = threadIdx.x & 31;
    if (warp >= NN) return;
    int n = warp;
    if (DOUT == 128) {
        float4 acc = *(const float4*)(g_T + (size_t)n * C + RR * DOUT + lane * 4);
        float4 bb = *(const float4*)(bias + lane * 4);
        acc.x += bb.x; acc.y += bb.y; acc.z += bb.z; acc.w += bb.w;
        int e0 = g_off[n], e1 = g_off[n + 1];
        for (int e = e0; e < e1; e++) {
            unsigned u = g_csr[e];
            int s = (int)(u & 0xFFFFFu);
            int et = (int)(u >> 20);
            float4 t4 = *(const float4*)(g_T + (size_t)s * C + et * DOUT + lane * 4);
            acc.x += t4.x; acc.y += t4.y; acc.z += t4.z; acc.w += t4.w;
        }
        float4 r;
        r.x = fmaxf(acc.x, 0.f); r.y = fmaxf(acc.y, 0.f);
        r.z = fmaxf(acc.z, 0.f); r.w = fmaxf(acc.w, 0.f);
        *(float4*)(Hout + (size_t)n * DOUT + lane * 4) = r;
    } else {  // DOUT == 64
        float2 acc = *(const float2*)(g_T + (size_t)n * C + RR * DOUT + lane * 2);
        float2 bb = *(const float2*)(bias + lane * 2);
        acc.x += bb.x; acc.y += bb.y;
        int e0 = g_off[n], e1 = g_off[n + 1];
        for (int e = e0; e < e1; e++) {
            unsigned u = g_csr[e];
            int s = (int)(u & 0xFFFFFu);
            int et = (int)(u >> 20);
            float2 t2 = *(const float2*)(g_T + (size_t)s * C + et * DOUT + lane * 2);
            acc.x += t2.x; acc.y += t2.y;
        }
        float2 r;
        r.x = fmaxf(acc.x, 0.f); r.y = fmaxf(acc.y, 0.f);
        *(float2*)(Hout + (size_t)n * DOUT + lane * 2) = r;
    }
}

// ---------------- final dense (64 -> 2) ---------------------------------------
__global__ void finalKernel(const float* __restrict__ H3, const float* __restrict__ Wd,
                            const float* __restrict__ bd) {
    int n = blockIdx.x * blockDim.x + threadIdx.x;
    if (n >= NN) return;
    float a0 = bd[0], a1 = bd[1];
    const float* hr = H3 + (size_t)n * OUTD;
#pragma unroll 8
    for (int o = 0; o < OUTD; o++) {
        float h = hr[o];
        a0 += h * Wd[o * 2 + 0];
        a1 += h * Wd[o * 2 + 1];
    }
    g_hf[n * 2 + 0] = a0;
    g_hf[n * 2 + 1] = a1;
}

// ---------------- edge scoring output -----------------------------------------
__global__ void outputKernel(const int* __restrict__ ei, float* __restrict__ out) {
    int p = blockIdx.x * blockDim.x + threadIdx.x;
    if (p >= PP) return;
    int u1 = ei[p * 4 + 0], v1 = ei[p * 4 + 1];
    int u2 = ei[p * 4 + 2], v2 = ei[p * 4 + 3];
    out[p * 2 + 0] = 0.5f * (g_hf[u1 * 2 + 0] + g_hf[v1 * 2 + 0]);
    out[p * 2 + 1] = 0.5f * (g_hf[u1 * 2 + 1] + g_hf[v1 * 2 + 1]);
    out[PP * 2 + p * 2 + 0] = 0.5f * (g_hf[u2 * 2 + 0] + g_hf[v2 * 2 + 0]);
    out[PP * 2 + p * 2 + 1] = 0.5f * (g_hf[u2 * 2 + 1] + g_hf[v2 * 2 + 1]);
}

// ---------------- launch ------------------------------------------------------
static inline int cdiv(int a, int b) { return (a + b - 1) / b; }

extern "C" void kernel_launch(void* const* d_in, const int* in_sizes, int n_in,
                              void* d_out, int out_size) {
    const float* h   = (const float*)d_in[0];
    const int* src   = (const int*)d_in[1];
    const int* dst   = (const int*)d_in[2];
    const int* et    = (const int*)d_in[3];
    const int* ei    = (const int*)d_in[4];
    const float* W[4] = { (const float*)d_in[5],  (const float*)d_in[8],
                          (const float*)d_in[11], (const float*)d_in[14] };
    const float* L[4] = { (const float*)d_in[6],  (const float*)d_in[9],
                          (const float*)d_in[12], (const float*)d_in[15] };
    const float* b[4] = { (const float*)d_in[7],  (const float*)d_in[10],
                          (const float*)d_in[13], (const float*)d_in[16] };
    const float* Wd = (const float*)d_in[17];
    const float* bd = (const float*)d_in[18];
    float* out = (float*)d_out;

    float *pHA, *pHB;
    cudaGetSymbolAddress((void**)&pHA, g_HA);
    cudaGetSymbolAddress((void**)&pHB, g_HB);

    // ---- CSR build (once per launch) ----
    zeroDegKernel<<<cdiv(NN + 1, 256), 256>>>();
    histKernel<<<cdiv(EE, 256), 256>>>(dst);
    scanKernel<<<1, 1024>>>();
    copyCurKernel<<<cdiv(NN, 256), 256>>>();
    scatterKernel<<<cdiv(EE, 256), 256>>>(src, dst, et);

    // ---- layers ----
    const int dins[4]  = { F_IN, HID, HID, HID };
    const int douts[4] = { HID, HID, HID, OUTD };
    const float* Hin = h;
    float* Houts[4] = { pHA, pHB, pHA, pHB };

    for (int li = 0; li < 4; li++) {
        int din = dins[li], dout = douts[li];
        int C = (RR + 1) * dout;
        buildBwKernel<<<cdiv(din * C, 256), 256>>>(W[li], L[li], din, dout);
        dim3 grid(cdiv(C, TN), cdiv(NN, TM));
        gemmKernel<<<grid, 256>>>(Hin, NN, din, C);
        int aggBlocks = cdiv(NN * 32, 256);
        if (dout == 128)
            aggKernel<128><<<aggBlocks, 256>>>(b[li], Houts[li]);
        else
            aggKernel<64><<<aggBlocks, 256>>>(b[li], Houts[li]);
        Hin = Houts[li];
    }

    finalKernel<<<cdiv(NN, 256), 256>>>(Houts[3], Wd, bd);
    outputKernel<<<cdiv(PP, 256), 256>>>(ei, out);
}

// round 3
// speedup vs baseline: 1.9501x; 1.9501x over previous
#include <cuda_runtime.h>
#include <cuda_bf16.h>
#include <cstdint>

// Problem constants
#define NN 100000
#define EE 1600000
#define RR 12
#define F_IN 16
#define HID 128
#define OUTD 64
#define PP 4096
#define CMAX ((RR + 1) * HID)  // 1664
#define C3 ((RR + 1) * OUTD)   // 832

// ---------------- scratch (device globals; no allocation allowed) -------------
__device__ float         g_T[(size_t)NN * CMAX];   // per-relation transformed feats
__device__ float         g_Hf32[(size_t)NN * OUTD];// layer3 output (fp32)
__device__ __nv_bfloat16 g_Ahi[(size_t)NN * HID];  // split activations (GEMM A)
__device__ __nv_bfloat16 g_Alo[(size_t)NN * HID];
__device__ __nv_bfloat16 g_BThi[CMAX * HID];       // split transposed weights [C][K]
__device__ __nv_bfloat16 g_BTlo[CMAX * HID];
__device__ float         g_Bw[F_IN * CMAX];        // layer0 SIMT weights
__device__ int           g_deg[NN + 1];
__device__ int           g_off[NN + 1];
__device__ int           g_cur[NN];
__device__ unsigned      g_csr[EE];                // packed src | (etype << 20)
__device__ float         g_hf[NN * 2];

// ======================= mma.sync helpers (sm_100 baseline ISA) ===============
__device__ __forceinline__ uint32_t smem_u32(const void* p) {
    return (uint32_t)__cvta_generic_to_shared(p);
}
__device__ __forceinline__ void ldm_x4(uint32_t* r, uint32_t addr) {
    asm volatile("ldmatrix.sync.aligned.m8n8.x4.shared.b16 {%0,%1,%2,%3}, [%4];"
        : "=r"(r[0]), "=r"(r[1]), "=r"(r[2]), "=r"(r[3]) : "r"(addr));
}
__device__ __forceinline__ void ldm_x2(uint32_t* r, uint32_t addr) {
    asm volatile("ldmatrix.sync.aligned.m8n8.x2.shared.b16 {%0,%1}, [%2];"
        : "=r"(r[0]), "=r"(r[1]) : "r"(addr));
}
__device__ __forceinline__ void mma_16816(float* d, const uint32_t* a, const uint32_t* b) {
    asm volatile("mma.sync.aligned.m16n8k16.row.col.f32.bf16.bf16.f32 "
        "{%0,%1,%2,%3}, {%4,%5,%6,%7}, {%8,%9}, {%0,%1,%2,%3};"
        : "+f"(d[0]), "+f"(d[1]), "+f"(d[2]), "+f"(d[3])
        : "r"(a[0]), "r"(a[1]), "r"(a[2]), "r"(a[3]), "r"(b[0]), "r"(b[1]));
}

// ---------------- CSR build ---------------------------------------------------
__global__ void zeroDegKernel() {
    int i = blockIdx.x * blockDim.x + threadIdx.x;
    if (i <= NN) g_deg[i] = 0;
}
__global__ void histKernel(const int* __restrict__ dst) {
    int e = blockIdx.x * blockDim.x + threadIdx.x;
    if (e < EE) atomicAdd(&g_deg[dst[e]], 1);
}
__global__ void scanKernel() {
    __shared__ int sh[1024];
    __shared__ int carry;
    int t = threadIdx.x;
    if (t == 0) carry = 0;
    __syncthreads();
    for (int base = 0; base < NN; base += 1024) {
        int i = base + t;
        int v = (i < NN) ? g_deg[i] : 0;
        sh[t] = v;
        __syncthreads();
        for (int s = 1; s < 1024; s <<= 1) {
            int tmp = (t >= s) ? sh[t - s] : 0;
            __syncthreads();
            sh[t] += tmp;
            __syncthreads();
        }
        int excl = sh[t] - v;
        if (i < NN) g_off[i] = carry + excl;
        int total = sh[1023];
        __syncthreads();
        if (t == 0) carry += total;
        __syncthreads();
    }
    if (t == 0) g_off[NN] = carry;
}
__global__ void copyCurKernel() {
    int i = blockIdx.x * blockDim.x + threadIdx.x;
    if (i < NN) g_cur[i] = g_off[i];
}
__global__ void scatterKernel(const int* __restrict__ src, const int* __restrict__ dst,
                              const int* __restrict__ et) {
    int e = blockIdx.x * blockDim.x + threadIdx.x;
    if (e >= EE) return;
    int d = dst[e];
    int pos = atomicAdd(&g_cur[d], 1);
    g_csr[pos] = (unsigned)src[e] | ((unsigned)et[e] << 20);
}

// ---------------- weights: layer0 SIMT concat, layers1-3 split transposed -----
__global__ void buildBwKernel(const float* __restrict__ W, const float* __restrict__ L,
                              int din, int dout) {
    int C = (RR + 1) * dout;
    int total = din * C;
    int idx = blockIdx.x * blockDim.x + threadIdx.x;
    if (idx >= total) return;
    int i = idx / C, c = idx % C;
    int r = c / dout, o = c % dout;
    g_Bw[idx] = (r < RR) ? W[((size_t)r * din + i) * dout + o] : L[(size_t)i * dout + o];
}
// BT[c][k] = W[r][k][o] (r=c/dout, o=c%dout), r==R -> L[k][o]; K=128 fixed
__global__ void buildBTKernel(const float* __restrict__ W, const float* __restrict__ L,
                              int dout) {
    int C = (RR + 1) * dout;
    int total = C * HID;
    int idx = blockIdx.x * blockDim.x + threadIdx.x;
    if (idx >= total) return;
    int c = idx >> 7, k = idx & 127;
    int r = c / dout, o = c % dout;
    float w = (r < RR) ? W[((size_t)r * HID + k) * dout + o] : L[(size_t)k * dout + o];
    __nv_bfloat16 hi = __float2bfloat16(w);
    __nv_bfloat16 lo = __float2bfloat16(w - __bfloat162float(hi));
    g_BThi[idx] = hi;
    g_BTlo[idx] = lo;
}

// ---------------- layer0 SIMT GEMM (K=16, memory-bound) -----------------------
#define TM 128
#define TN 128
#define TK 16
__global__ void gemmKernel(const float* __restrict__ A, int M, int K, int C) {
    __shared__ float As[TK][TM];
    __shared__ float Bs[TK][TN];
    int tid = threadIdx.x;
    int tx = tid & 15, ty = tid >> 4;
    int row0 = blockIdx.y * TM, col0 = blockIdx.x * TN;
    float acc[8][8];
#pragma unroll
    for (int i = 0; i < 8; i++)
#pragma unroll
        for (int j = 0; j < 8; j++) acc[i][j] = 0.f;
    for (int kt = 0; kt < K; kt += TK) {
        for (int e = tid; e < TM * TK; e += 256) {
            int r = e / TK, k = e % TK;
            int gr = row0 + r;
            As[k][r] = (gr < M) ? A[(size_t)gr * K + kt + k] : 0.f;
        }
        for (int e = tid; e < TK * TN; e += 256) {
            int k = e / TN, c = e % TN;
            int gc = col0 + c;
            Bs[k][c] = (gc < C) ? g_Bw[(size_t)(kt + k) * C + gc] : 0.f;
        }
        __syncthreads();
#pragma unroll
        for (int k = 0; k < TK; k++) {
            float a[8], b[8];
#pragma unroll
            for (int i = 0; i < 8; i++) a[i] = As[k][ty + 16 * i];
#pragma unroll
            for (int j = 0; j < 8; j++) b[j] = Bs[k][tx + 16 * j];
#pragma unroll
            for (int i = 0; i < 8; i++)
#pragma unroll
                for (int j = 0; j < 8; j++) acc[i][j] += a[i] * b[j];
        }
        __syncthreads();
    }
#pragma unroll
    for (int i = 0; i < 8; i++) {
        int gr = row0 + ty + 16 * i;
        if (gr >= M) continue;
#pragma unroll
        for (int j = 0; j < 8; j++) {
            int gc = col0 + tx + 16 * j;
            if (gc < C) g_T[(size_t)gr * C + gc] = acc[i][j];
        }
    }
}

// ---------------- HMMA bf16x3 GEMM: T = A[M,128] @ BT[C,128]^T ---------------
// CTA tile 64x128, K=128 resident in SMEM, no mainloop. 2 CTAs/SM overlap
// load phase of one with MMA phase of the other.
#define BM 64
#define BN 128
#define PAD 136   // bf16 elements per smem row (272B -> conflict-free ldmatrix)
#define MMA_SMEM ((2 * BM + 2 * BN) * PAD * 2)  // 104448 bytes

__global__ __launch_bounds__(256, 2) void mmaGemmKernel(int M, int C) {
    extern __shared__ __nv_bfloat16 sm[];
    __nv_bfloat16* sAhi = sm;
    __nv_bfloat16* sAlo = sAhi + BM * PAD;
    __nv_bfloat16* sBhi = sAlo + BM * PAD;
    __nv_bfloat16* sBlo = sBhi + BN * PAD;

    int tid = threadIdx.x, wid = tid >> 5, lane = tid & 31;
    int row0 = blockIdx.y * BM, colT0 = blockIdx.x * BN;

    const uint4 z4 = make_uint4(0, 0, 0, 0);
    // A: BM rows x 128 cols, hi+lo (16 uint4-chunks per row)
    for (int c = tid; c < BM * 16; c += 256) {
        int r = c >> 4, col0 = (c & 15) << 3;
        int gr = row0 + r;
        uint4 vh = z4, vl = z4;
        if (gr < M) {
            vh = *(const uint4*)(g_Ahi + (size_t)gr * HID + col0);
            vl = *(const uint4*)(g_Alo + (size_t)gr * HID + col0);
        }
        *(uint4*)(sAhi + r * PAD + col0) = vh;
        *(uint4*)(sAlo + r * PAD + col0) = vl;
    }
    // B: BN rows (output cols) x 128, hi+lo
    for (int c = tid; c < BN * 16; c += 256) {
        int r = c >> 4, col0 = (c & 15) << 3;
        int gc = colT0 + r;
        uint4 wh = z4, wl = z4;
        if (gc < C) {
            wh = *(const uint4*)(g_BThi + (size_t)gc * HID + col0);
            wl = *(const uint4*)(g_BTlo + (size_t)gc * HID + col0);
        }
        *(uint4*)(sBhi + r * PAD + col0) = wh;
        *(uint4*)(sBlo + r * PAD + col0) = wl;
    }
    __syncthreads();

    int wrow = wid >> 2, wcol = wid & 3;  // 2 x 4 warp grid -> 32x32 per warp
    float acc[2][4][4];
#pragma unroll
    for (int mi = 0; mi < 2; mi++)
#pragma unroll
        for (int ni = 0; ni < 4; ni++)
#pragma unroll
            for (int j = 0; j < 4; j++) acc[mi][ni][j] = 0.f;

    int lrA = lane & 15;               // A ldmatrix row within m16
    int lkA = (lane >> 4) << 3;        // A ldmatrix k offset (0/8)
    int lnB = lane & 7;                // B ldmatrix row within n8
    int lkB = ((lane >> 3) & 1) << 3;  // B ldmatrix k offset (0/8)

#pragma unroll
    for (int ks = 0; ks < 8; ks++) {
        int k0 = ks << 4;
        uint32_t bh[4][2], bl[4][2];
#pragma unroll
        for (int ni = 0; ni < 4; ni++) {
            int n = wcol * 32 + ni * 8 + lnB;
            ldm_x2(bh[ni], smem_u32(sBhi + n * PAD + k0 + lkB));
            ldm_x2(bl[ni], smem_u32(sBlo + n * PAD + k0 + lkB));
        }
#pragma unroll
        for (int mi = 0; mi < 2; mi++) {
            int m = wrow * 32 + mi * 16 + lrA;
            uint32_t ah[4], al[4];
            ldm_x4(ah, smem_u32(sAhi + m * PAD + k0 + lkA));
            ldm_x4(al, smem_u32(sAlo + m * PAD + k0 + lkA));
#pragma unroll
            for (int ni = 0; ni < 4; ni++) {
                mma_16816(acc[mi][ni], ah, bh[ni]);
                mma_16816(acc[mi][ni], ah, bl[ni]);
                mma_16816(acc[mi][ni], al, bh[ni]);
            }
        }
    }

    // epilogue: D fragment layout -> g_T
#pragma unroll
    for (int mi = 0; mi < 2; mi++) {
        int gr0 = row0 + wrow * 32 + mi * 16 + (lane >> 2);
#pragma unroll
        for (int ni = 0; ni < 4; ni++) {
            int gc = colT0 + wcol * 32 + ni * 8 + (lane & 3) * 2;
            if (gc < C) {
                if (gr0 < M) {
                    float2 v = make_float2(acc[mi][ni][0], acc[mi][ni][1]);
                    *(float2*)(g_T + (size_t)gr0 * C + gc) = v;
                }
                if (gr0 + 8 < M) {
                    float2 v = make_float2(acc[mi][ni][2], acc[mi][ni][3]);
                    *(float2*)(g_T + (size_t)(gr0 + 8) * C + gc) = v;
                }
            }
        }
    }
}

// ---------------- aggregation (layers 0-2): gather + bias + relu + bf16 split -
__global__ void aggSplitKernel(const float* __restrict__ bias) {
    const int C = CMAX;
    int warp = (blockIdx.x * blockDim.x + threadIdx.x) >> 5;
    int lane = threadIdx.x & 31;
    if (warp >= NN) return;
    int n = warp;
    float4 acc = *(const float4*)(g_T + (size_t)n * C + RR * HID + lane * 4);
    float4 bb = *(const float4*)(bias + lane * 4);
    acc.x += bb.x; acc.y += bb.y; acc.z += bb.z; acc.w += bb.w;
    int e0 = g_off[n], e1 = g_off[n + 1];
    for (int e = e0; e < e1; e++) {
        unsigned u = g_csr[e];
        int s = (int)(u & 0xFFFFFu);
        int et = (int)(u >> 20);
        float4 t4 = *(const float4*)(g_T + (size_t)s * C + et * HID + lane * 4);
        acc.x += t4.x; acc.y += t4.y; acc.z += t4.z; acc.w += t4.w;
    }
    float rx = fmaxf(acc.x, 0.f), ry = fmaxf(acc.y, 0.f);
    float rz = fmaxf(acc.z, 0.f), rw = fmaxf(acc.w, 0.f);
    union { __nv_bfloat16 b[4]; uint2 u; } hv, lv;
    hv.b[0] = __float2bfloat16(rx); lv.b[0] = __float2bfloat16(rx - __bfloat162float(hv.b[0]));
    hv.b[1] = __float2bfloat16(ry); lv.b[1] = __float2bfloat16(ry - __bfloat162float(hv.b[1]));
    hv.b[2] = __float2bfloat16(rz); lv.b[2] = __float2bfloat16(rz - __bfloat162float(hv.b[2]));
    hv.b[3] = __float2bfloat16(rw); lv.b[3] = __float2bfloat16(rw - __bfloat162float(hv.b[3]));
    *(uint2*)(g_Ahi + (size_t)n * HID + lane * 4) = hv.u;
    *(uint2*)(g_Alo + (size_t)n * HID + lane * 4) = lv.u;
}

// ---------------- aggregation layer3 (dout=64, fp32 out) ----------------------
__global__ void agg64Kernel(const float* __restrict__ bias) {
    const int C = C3;
    int warp = (blockIdx.x * blockDim.x + threadIdx.x) >> 5;
    int lane = threadIdx.x & 31;
    if (warp >= NN) return;
    int n = warp;
    float2 acc = *(const float2*)(g_T + (size_t)n * C + RR * OUTD + lane * 2);
    float2 bb = *(const float2*)(bias + lane * 2);
    acc.x += bb.x; acc.y += bb.y;
    int e0 = g_off[n], e1 = g_off[n + 1];
    for (int e = e0; e < e1; e++) {
        unsigned u = g_csr[e];
        int s = (int)(u & 0xFFFFFu);
        int et = (int)(u >> 20);
        float2 t2 = *(const float2*)(g_T + (size_t)s * C + et * OUTD + lane * 2);
        acc.x += t2.x; acc.y += t2.y;
    }
    float2 r;
    r.x = fmaxf(acc.x, 0.f); r.y = fmaxf(acc.y, 0.f);
    *(float2*)(g_Hf32 + (size_t)n * OUTD + lane * 2) = r;
}

// ---------------- final dense (64 -> 2) ---------------------------------------
__global__ void finalKernel(const float* __restrict__ Wd, const float* __restrict__ bd) {
    int n = blockIdx.x * blockDim.x + threadIdx.x;
    if (n >= NN) return;
    float a0 = bd[0], a1 = bd[1];
    const float* hr = g_Hf32 + (size_t)n * OUTD;
#pragma unroll 8
    for (int o = 0; o < OUTD; o++) {
        float h = hr[o];
        a0 += h * Wd[o * 2 + 0];
        a1 += h * Wd[o * 2 + 1];
    }
    g_hf[n * 2 + 0] = a0;
    g_hf[n * 2 + 1] = a1;
}

// ---------------- edge scoring output -----------------------------------------
__global__ void outputKernel(const int* __restrict__ ei, float* __restrict__ out) {
    int p = blockIdx.x * blockDim.x + threadIdx.x;
    if (p >= PP) return;
    int u1 = ei[p * 4 + 0], v1 = ei[p * 4 + 1];
    int u2 = ei[p * 4 + 2], v2 = ei[p * 4 + 3];
    out[p * 2 + 0] = 0.5f * (g_hf[u1 * 2 + 0] + g_hf[v1 * 2 + 0]);
    out[p * 2 + 1] = 0.5f * (g_hf[u1 * 2 + 1] + g_hf[v1 * 2 + 1]);
    out[PP * 2 + p * 2 + 0] = 0.5f * (g_hf[u2 * 2 + 0] + g_hf[v2 * 2 + 0]);
    out[PP * 2 + p * 2 + 1] = 0.5f * (g_hf[u2 * 2 + 1] + g_hf[v2 * 2 + 1]);
}

// ---------------- launch ------------------------------------------------------
static inline int cdiv(int a, int b) { return (a + b - 1) / b; }

extern "C" void kernel_launch(void* const* d_in, const int* in_sizes, int n_in,
                              void* d_out, int out_size) {
    const float* h   = (const float*)d_in[0];
    const int* src   = (const int*)d_in[1];
    const int* dst   = (const int*)d_in[2];
    const int* et    = (const int*)d_in[3];
    const int* ei    = (const int*)d_in[4];
    const float* W[4] = { (const float*)d_in[5],  (const float*)d_in[8],
                          (const float*)d_in[11], (const float*)d_in[14] };
    const float* L[4] = { (const float*)d_in[6],  (const float*)d_in[9],
                          (const float*)d_in[12], (const float*)d_in[15] };
    const float* b[4] = { (const float*)d_in[7],  (const float*)d_in[10],
                          (const float*)d_in[13], (const float*)d_in[16] };
    const float* Wd = (const float*)d_in[17];
    const float* bd = (const float*)d_in[18];
    float* out = (float*)d_out;

    cudaFuncSetAttribute(mmaGemmKernel,
                         cudaFuncAttributeMaxDynamicSharedMemorySize, MMA_SMEM);

    // ---- CSR build ----
    zeroDegKernel<<<cdiv(NN + 1, 256), 256>>>();
    histKernel<<<cdiv(EE, 256), 256>>>(dst);
    scanKernel<<<1, 1024>>>();
    copyCurKernel<<<cdiv(NN, 256), 256>>>();
    scatterKernel<<<cdiv(EE, 256), 256>>>(src, dst, et);

    int mtiles = cdiv(NN, BM);
    int aggBlocks = cdiv(NN * 32, 256);

    // ---- layer 0: SIMT GEMM (K=16), split-agg ----
    buildBwKernel<<<cdiv(F_IN * CMAX, 256), 256>>>(W[0], L[0], F_IN, HID);
    {
        dim3 grid(cdiv(CMAX, TN), cdiv(NN, TM));
        gemmKernel<<<grid, 256>>>(h, NN, F_IN, CMAX);
    }
    aggSplitKernel<<<aggBlocks, 256>>>(b[0]);

    // ---- layers 1,2: HMMA bf16x3 GEMM (C=1664), split-agg ----
    for (int li = 1; li <= 2; li++) {
        buildBTKernel<<<cdiv(CMAX * HID, 256), 256>>>(W[li], L[li], HID);
        dim3 grid(cdiv(CMAX, BN), mtiles);
        mmaGemmKernel<<<grid, 256, MMA_SMEM>>>(NN, CMAX);
        aggSplitKernel<<<aggBlocks, 256>>>(b[li]);
    }

    // ---- layer 3: HMMA GEMM (C=832), fp32 agg ----
    buildBTKernel<<<cdiv(C3 * HID, 256), 256>>>(W[3], L[3], OUTD);
    {
        dim3 grid(cdiv(C3, BN), mtiles);
        mmaGemmKernel<<<grid, 256, MMA_SMEM>>>(NN, C3);
    }
    agg64Kernel<<<aggBlocks, 256>>>(b[3]);

    finalKernel<<<cdiv(NN, 256), 256>>>(Wd, bd);
    outputKernel<<<cdiv(PP, 256), 256>>>(ei, out);
}

// round 4
// speedup vs baseline: 2.3344x; 1.1971x over previous
#include <cuda_runtime.h>
#include <cuda_bf16.h>
#include <cstdint>

// Problem constants
#define NN 100000
#define EE 1600000
#define RR 12
#define F_IN 16
#define HID 128
#define OUTD 64
#define PP 4096
#define NK (NN * RR)            // 1,200,000 (dst,etype) segments
#define MT 100096               // NN padded to 64 (1564 * 64)
#define KBIG ((RR + 1) * HID)   // 1664
#define K0P 256                 // layer0 K padded (13*16=208 -> 256)
#define NB1 ((NK + 1023) / 1024) // 1172 scan blocks

// ---------------- scratch (device globals; no allocation allowed) -------------
__device__ __nv_bfloat16 g_Ahi[(size_t)MT * KBIG];  // GEMM A, hi split
__device__ __nv_bfloat16 g_Alo[(size_t)MT * KBIG];  // GEMM A, lo split
__device__ __nv_bfloat16 g_BThi[HID * KBIG];        // B^T [out_col][k], hi
__device__ __nv_bfloat16 g_BTlo[HID * KBIG];        // B^T [out_col][k], lo
__device__ float         g_HA[(size_t)NN * HID];
__device__ float         g_HB[(size_t)NN * HID];
__device__ float         g_Hf32[(size_t)NN * OUTD];
__device__ int           g_deg[NK + 2];
__device__ int           g_off[NK + 2];
__device__ int           g_cur[NK + 2];
__device__ int           g_bsum[NB1 + 2];
__device__ int           g_boff[NB1 + 2];
__device__ unsigned      g_csr[EE];                 // src only (segments encode dst,etype)
__device__ float         g_hf[NN * 2];

// ======================= mma.sync helpers (sm_100 baseline ISA) ===============
__device__ __forceinline__ uint32_t smem_u32(const void* p) {
    return (uint32_t)__cvta_generic_to_shared(p);
}
__device__ __forceinline__ void ldm_x4(uint32_t* r, uint32_t addr) {
    asm volatile("ldmatrix.sync.aligned.m8n8.x4.shared.b16 {%0,%1,%2,%3}, [%4];"
        : "=r"(r[0]), "=r"(r[1]), "=r"(r[2]), "=r"(r[3]) : "r"(addr));
}
__device__ __forceinline__ void mma_16816(float* d, const uint32_t* a, const uint32_t* b) {
    asm volatile("mma.sync.aligned.m16n8k16.row.col.f32.bf16.bf16.f32 "
        "{%0,%1,%2,%3}, {%4,%5,%6,%7}, {%8,%9}, {%0,%1,%2,%3};"
        : "+f"(d[0]), "+f"(d[1]), "+f"(d[2]), "+f"(d[3])
        : "r"(a[0]), "r"(a[1]), "r"(a[2]), "r"(a[3]), "r"(b[0]), "r"(b[1]));
}
__device__ __forceinline__ void cp16(uint32_t dst, const void* src) {
    asm volatile("cp.async.cg.shared.global [%0], [%1], 16;" :: "r"(dst), "l"(src));
}
__device__ __forceinline__ void cp_commit() { asm volatile("cp.async.commit_group;"); }
template <int N>
__device__ __forceinline__ void cp_wait() { asm volatile("cp.async.wait_group %0;" :: "n"(N)); }

// ---------------- CSR build over (dst*12 + etype) keys ------------------------
__global__ void zeroDegKernel() {
    int i = blockIdx.x * blockDim.x + threadIdx.x;
    if (i <= NK) g_deg[i] = 0;
}
__global__ void histKernel(const int* __restrict__ dst, const int* __restrict__ et) {
    int e = blockIdx.x * blockDim.x + threadIdx.x;
    if (e < EE) atomicAdd(&g_deg[dst[e] * RR + et[e]], 1);
}
// per-block inclusive scan of 1024; block sums out
__global__ void scanK1() {
    __shared__ int sh[1024];
    int t = threadIdx.x;
    int i = blockIdx.x * 1024 + t;
    int v = (i < NK) ? g_deg[i] : 0;
    sh[t] = v;
    __syncthreads();
    for (int s = 1; s < 1024; s <<= 1) {
        int tmp = (t >= s) ? sh[t - s] : 0;
        __syncthreads();
        sh[t] += tmp;
        __syncthreads();
    }
    if (i < NK) g_off[i] = sh[t];  // inclusive within block (fixed up in scanK3)
    if (t == 1023) g_bsum[blockIdx.x] = sh[1023];
}
// exclusive scan of block sums (single block, 2 chunks with carry)
__global__ void scanK2() {
    __shared__ int sh[1024];
    __shared__ int carry;
    int t = threadIdx.x;
    if (t == 0) carry = 0;
    __syncthreads();
    for (int base = 0; base < NB1; base += 1024) {
        int i = base + t;
        int v = (i < NB1) ? g_bsum[i] : 0;
        sh[t] = v;
        __syncthreads();
        for (int s = 1; s < 1024; s <<= 1) {
            int tmp = (t >= s) ? sh[t - s] : 0;
            __syncthreads();
            sh[t] += tmp;
            __syncthreads();
        }
        if (i < NB1) g_boff[i] = carry + sh[t] - v;
        int tot = sh[1023];
        __syncthreads();
        if (t == 0) carry += tot;
        __syncthreads();
    }
    if (t == 0) g_off[NK] = carry;
}
// convert to global exclusive offsets; also seed g_cur
__global__ void scanK3() {
    int i = blockIdx.x * blockDim.x + threadIdx.x;
    if (i >= NK) return;
    int excl = g_off[i] + g_boff[i >> 10] - g_deg[i];
    g_off[i] = excl;
    g_cur[i] = excl;
}
__global__ void scatterKernel(const int* __restrict__ src, const int* __restrict__ dst,
                              const int* __restrict__ et) {
    int e = blockIdx.x * blockDim.x + threadIdx.x;
    if (e >= EE) return;
    int key = dst[e] * RR + et[e];
    int pos = atomicAdd(&g_cur[key], 1);
    g_csr[pos] = (unsigned)src[e];
}

// ---------------- weights: BT[o][kk], kk = r*din + i (r==12 -> self loop L) ---
__global__ void buildBTKernel(const float* __restrict__ W, const float* __restrict__ L,
                              int K, int NO, int din) {
    int idx = blockIdx.x * blockDim.x + threadIdx.x;
    if (idx >= NO * K) return;
    int o = idx / K, kk = idx % K;
    int r = kk / din, i = kk % din;
    float w = 0.f;
    if (r < RR)       w = W[((size_t)r * din + i) * NO + o];
    else if (r == RR) w = L[(size_t)i * NO + o];
    __nv_bfloat16 hi = __float2bfloat16(w);
    __nv_bfloat16 lo = __float2bfloat16(w - __bfloat162float(hi));
    g_BThi[idx] = hi;
    g_BTlo[idx] = lo;
}

// ---------------- aggregation layer0 (din=16): A[n] = [agg_r | h | 0pad] ------
__global__ void agg0Kernel(const float* __restrict__ h0) {
    int warp = (blockIdx.x * blockDim.x + threadIdx.x) >> 5;
    int lane = threadIdx.x & 31;
    if (warp >= NN) return;
    int n = warp;
    size_t ab = (size_t)n * K0P;
#pragma unroll 1
    for (int r = 0; r < RR; r++) {
        int e0 = g_off[n * RR + r], e1 = g_off[n * RR + r + 1];
        float acc = 0.f;
        for (int e = e0; e < e1; e++) {
            unsigned s = g_csr[e];
            if (lane < 16) acc += __ldg(h0 + (size_t)s * F_IN + lane);
        }
        if (lane < 16) {
            __nv_bfloat16 hi = __float2bfloat16(acc);
            g_Ahi[ab + r * F_IN + lane] = hi;
            g_Alo[ab + r * F_IN + lane] = __float2bfloat16(acc - __bfloat162float(hi));
        }
    }
    if (lane < 16) {
        float v = __ldg(h0 + (size_t)n * F_IN + lane);
        __nv_bfloat16 hi = __float2bfloat16(v);
        g_Ahi[ab + RR * F_IN + lane] = hi;
        g_Alo[ab + RR * F_IN + lane] = __float2bfloat16(v - __bfloat162float(hi));
    }
    if (lane < 24) {  // zero pad cols 208..255
        *(uint32_t*)&g_Ahi[ab + 208 + lane * 2] = 0u;
        *(uint32_t*)&g_Alo[ab + 208 + lane * 2] = 0u;
    }
}

// ---------------- aggregation din=128 layers: A[n] = [agg_0..11 | h] ----------
__global__ void agg128Kernel(const float* __restrict__ h) {
    int warp = (blockIdx.x * blockDim.x + threadIdx.x) >> 5;
    int lane = threadIdx.x & 31;
    if (warp >= NN) return;
    int n = warp;
    size_t ab = (size_t)n * KBIG;
#pragma unroll 1
    for (int r = 0; r < RR; r++) {
        int e0 = g_off[n * RR + r], e1 = g_off[n * RR + r + 1];
        float4 acc = make_float4(0.f, 0.f, 0.f, 0.f);
        for (int e = e0; e < e1; e++) {
            unsigned s = g_csr[e];
            float4 v = *(const float4*)(h + (size_t)s * HID + lane * 4);
            acc.x += v.x; acc.y += v.y; acc.z += v.z; acc.w += v.w;
        }
        union { __nv_bfloat16 b[4]; uint2 u; } hv, lv;
        hv.b[0] = __float2bfloat16(acc.x); lv.b[0] = __float2bfloat16(acc.x - __bfloat162float(hv.b[0]));
        hv.b[1] = __float2bfloat16(acc.y); lv.b[1] = __float2bfloat16(acc.y - __bfloat162float(hv.b[1]));
        hv.b[2] = __float2bfloat16(acc.z); lv.b[2] = __float2bfloat16(acc.z - __bfloat162float(hv.b[2]));
        hv.b[3] = __float2bfloat16(acc.w); lv.b[3] = __float2bfloat16(acc.w - __bfloat162float(hv.b[3]));
        *(uint2*)&g_Ahi[ab + r * HID + lane * 4] = hv.u;
        *(uint2*)&g_Alo[ab + r * HID + lane * 4] = lv.u;
    }
    {
        float4 v = *(const float4*)(h + (size_t)n * HID + lane * 4);
        union { __nv_bfloat16 b[4]; uint2 u; } hv, lv;
        hv.b[0] = __float2bfloat16(v.x); lv.b[0] = __float2bfloat16(v.x - __bfloat162float(hv.b[0]));
        hv.b[1] = __float2bfloat16(v.y); lv.b[1] = __float2bfloat16(v.y - __bfloat162float(hv.b[1]));
        hv.b[2] = __float2bfloat16(v.z); lv.b[2] = __float2bfloat16(v.z - __bfloat162float(hv.b[2]));
        hv.b[3] = __float2bfloat16(v.w); lv.b[3] = __float2bfloat16(v.w - __bfloat162float(hv.b[3]));
        *(uint2*)&g_Ahi[ab + RR * HID + lane * 4] = hv.u;
        *(uint2*)&g_Alo[ab + RR * HID + lane * 4] = lv.u;
    }
}

// ---------------- pipelined HMMA bf16x3 GEMM: out = relu(A @ BT^T + bias) -----
// CTA tile 64(M) x 128(N); K streamed in KT=64 chunks; cp.async double buffer.
// smem stage: sAhi 9216 | sAlo 9216 | sBhi 18432 | sBlo 18432 = 55296 B; x2 stages.
#define STAGE_B 55296
#define GEMM_SMEM (2 * STAGE_B)

__global__ __launch_bounds__(256, 2) void gemmK(
    const __nv_bfloat16* __restrict__ Ahi, const __nv_bfloat16* __restrict__ Alo,
    const __nv_bfloat16* __restrict__ BThi, const __nv_bfloat16* __restrict__ BTlo,
    int K, int NO, const float* __restrict__ bias, float* __restrict__ out)
{
    extern __shared__ char smem[];
    int tid = threadIdx.x, wid = tid >> 5, lane = tid & 31;
    int row0 = blockIdx.x * 64;
    int wrow = wid & 1, wcol = wid >> 1;   // 2 m-warps x 4 n-warps (32x32 tiles)

    // zero-fill B tail rows once (both stages) when NO < 128
    if (NO < 128) {
#pragma unroll
        for (int reg = 0; reg < 4; reg++) {
            uint32_t* base = (uint32_t*)(smem + (reg >> 1) * STAGE_B + 18432
                                         + (reg & 1) * 18432 + NO * 144);
            for (int i = tid; i < (128 - NO) * 36; i += 256) base[i] = 0u;
        }
    }

    auto loadStage = [&](int s, int k0) {
        char* st = smem + s * STAGE_B;
        for (int c = tid; c < 512; c += 256) {          // A: 64 rows x 4 chunks(16B) x2
            int row = c >> 3, kc = (c & 7) << 3;
            size_t g = (size_t)(row0 + row) * K + k0 + kc;
            cp16(smem_u32(st + row * 144 + kc * 2), Ahi + g);
            cp16(smem_u32(st + 9216 + row * 144 + kc * 2), Alo + g);
        }
        for (int c = tid; c < 1024; c += 256) {         // B: 128 rows
            int row = c >> 3, kc = (c & 7) << 3;
            if (row < NO) {
                size_t g = (size_t)row * K + k0 + kc;
                cp16(smem_u32(st + 18432 + row * 144 + kc * 2), BThi + g);
                cp16(smem_u32(st + 36864 + row * 144 + kc * 2), BTlo + g);
            }
        }
    };

    float acc[2][4][4];
#pragma unroll
    for (int mi = 0; mi < 2; mi++)
#pragma unroll
        for (int nj = 0; nj < 4; nj++)
#pragma unroll
            for (int j = 0; j < 4; j++) acc[mi][nj][j] = 0.f;

    int KITERS = K >> 6;
    loadStage(0, 0);
    cp_commit();

    for (int kt = 0; kt < KITERS; kt++) {
        if (kt + 1 < KITERS) {
            loadStage((kt + 1) & 1, (kt + 1) << 6);
            cp_commit();
            cp_wait<1>();
        } else {
            cp_wait<0>();
        }
        __syncthreads();
        uint32_t uA = smem_u32(smem + (kt & 1) * STAGE_B);
        uint32_t uAhi = uA, uAlo = uA + 9216, uBhi = uA + 18432, uBlo = uA + 36864;
#pragma unroll
        for (int k16 = 0; k16 < 4; k16++) {
            int koA = (k16 << 4) + ((lane >> 4) << 3);
            int rowA = wrow * 32 + (lane & 15);
            uint32_t ah[2][4], al[2][4];
            ldm_x4(ah[0], uAhi + rowA * 144 + koA * 2);
            ldm_x4(ah[1], uAhi + (rowA + 16) * 144 + koA * 2);
            ldm_x4(al[0], uAlo + rowA * 144 + koA * 2);
            ldm_x4(al[1], uAlo + (rowA + 16) * 144 + koA * 2);
            int koB = (k16 << 4) + (((lane >> 3) & 1) << 3);
            int rowB = wcol * 32 + ((lane >> 4) << 3) + (lane & 7);
            uint32_t bh[2][4], bl[2][4];
            ldm_x4(bh[0], uBhi + rowB * 144 + koB * 2);
            ldm_x4(bh[1], uBhi + (rowB + 16) * 144 + koB * 2);
            ldm_x4(bl[0], uBlo + rowB * 144 + koB * 2);
            ldm_x4(bl[1], uBlo + (rowB + 16) * 144 + koB * 2);
#pragma unroll
            for (int mi = 0; mi < 2; mi++)
#pragma unroll
                for (int nj = 0; nj < 4; nj++) {
                    const uint32_t* bhf = &bh[nj >> 1][(nj & 1) * 2];
                    const uint32_t* blf = &bl[nj >> 1][(nj & 1) * 2];
                    mma_16816(acc[mi][nj], ah[mi], bhf);
                    mma_16816(acc[mi][nj], ah[mi], blf);
                    mma_16816(acc[mi][nj], al[mi], bhf);
                }
        }
        __syncthreads();
    }

    // epilogue: bias + relu + fp32 store
#pragma unroll
    for (int mi = 0; mi < 2; mi++) {
        int gr = row0 + wrow * 32 + mi * 16 + (lane >> 2);
#pragma unroll
        for (int nj = 0; nj < 4; nj++) {
            int gc = wcol * 32 + nj * 8 + (lane & 3) * 2;
            if (gc < NO) {
                float bx = __ldg(bias + gc), by = __ldg(bias + gc + 1);
                if (gr < NN) {
                    float2 v = make_float2(fmaxf(acc[mi][nj][0] + bx, 0.f),
                                           fmaxf(acc[mi][nj][1] + by, 0.f));
                    *(float2*)(out + (size_t)gr * NO + gc) = v;
                }
                if (gr + 8 < NN) {
                    float2 v = make_float2(fmaxf(acc[mi][nj][2] + bx, 0.f),
                                           fmaxf(acc[mi][nj][3] + by, 0.f));
                    *(float2*)(out + (size_t)(gr + 8) * NO + gc) = v;
                }
            }
        }
    }
}

// ---------------- final dense (64 -> 2) ---------------------------------------
__global__ void finalKernel(const float* __restrict__ Wd, const float* __restrict__ bd) {
    int n = blockIdx.x * blockDim.x + threadIdx.x;
    if (n >= NN) return;
    float a0 = bd[0], a1 = bd[1];
    const float* hr = g_Hf32 + (size_t)n * OUTD;
#pragma unroll 8
    for (int o = 0; o < OUTD; o++) {
        float h = hr[o];
        a0 += h * Wd[o * 2 + 0];
        a1 += h * Wd[o * 2 + 1];
    }
    g_hf[n * 2 + 0] = a0;
    g_hf[n * 2 + 1] = a1;
}

// ---------------- edge scoring output -----------------------------------------
__global__ void outputKernel(const int* __restrict__ ei, float* __restrict__ out) {
    int p = blockIdx.x * blockDim.x + threadIdx.x;
    if (p >= PP) return;
    int u1 = ei[p * 4 + 0], v1 = ei[p * 4 + 1];
    int u2 = ei[p * 4 + 2], v2 = ei[p * 4 + 3];
    out[p * 2 + 0] = 0.5f * (g_hf[u1 * 2 + 0] + g_hf[v1 * 2 + 0]);
    out[p * 2 + 1] = 0.5f * (g_hf[u1 * 2 + 1] + g_hf[v1 * 2 + 1]);
    out[PP * 2 + p * 2 + 0] = 0.5f * (g_hf[u2 * 2 + 0] + g_hf[v2 * 2 + 0]);
    out[PP * 2 + p * 2 + 1] = 0.5f * (g_hf[u2 * 2 + 1] + g_hf[v2 * 2 + 1]);
}

// ---------------- launch ------------------------------------------------------
static inline int cdiv(int a, int b) { return (a + b - 1) / b; }

extern "C" void kernel_launch(void* const* d_in, const int* in_sizes, int n_in,
                              void* d_out, int out_size) {
    const float* h0  = (const float*)d_in[0];
    const int* src   = (const int*)d_in[1];
    const int* dst   = (const int*)d_in[2];
    const int* et    = (const int*)d_in[3];
    const int* ei    = (const int*)d_in[4];
    const float* W[4] = { (const float*)d_in[5],  (const float*)d_in[8],
                          (const float*)d_in[11], (const float*)d_in[14] };
    const float* L[4] = { (const float*)d_in[6],  (const float*)d_in[9],
                          (const float*)d_in[12], (const float*)d_in[15] };
    const float* b[4] = { (const float*)d_in[7],  (const float*)d_in[10],
                          (const float*)d_in[13], (const float*)d_in[16] };
    const float* Wd = (const float*)d_in[17];
    const float* bd = (const float*)d_in[18];
    float* out = (float*)d_out;

    cudaFuncSetAttribute(gemmK, cudaFuncAttributeMaxDynamicSharedMemorySize, GEMM_SMEM);

    __nv_bfloat16 *pAhi, *pAlo, *pBThi, *pBTlo;
    float *pHA, *pHB, *pHf;
    cudaGetSymbolAddress((void**)&pAhi, g_Ahi);
    cudaGetSymbolAddress((void**)&pAlo, g_Alo);
    cudaGetSymbolAddress((void**)&pBThi, g_BThi);
    cudaGetSymbolAddress((void**)&pBTlo, g_BTlo);
    cudaGetSymbolAddress((void**)&pHA, g_HA);
    cudaGetSymbolAddress((void**)&pHB, g_HB);
    cudaGetSymbolAddress((void**)&pHf, g_Hf32);

    // ---- CSR over (dst*12+etype) ----
    zeroDegKernel<<<cdiv(NK + 1, 256), 256>>>();
    histKernel<<<cdiv(EE, 256), 256>>>(dst, et);
    scanK1<<<NB1, 1024>>>();
    scanK2<<<1, 1024>>>();
    scanK3<<<cdiv(NK, 256), 256>>>();
    scatterKernel<<<cdiv(EE, 256), 256>>>(src, dst, et);

    int aggBlocks = cdiv(NN * 32, 256);
    int gemmBlocks = MT / 64;  // 1564

    // ---- layer 0: din=16, K=256 ----
    buildBTKernel<<<cdiv(HID * K0P, 256), 256>>>(W[0], L[0], K0P, HID, F_IN);
    agg0Kernel<<<aggBlocks, 256>>>(h0);
    gemmK<<<gemmBlocks, 256, GEMM_SMEM>>>(pAhi, pAlo, pBThi, pBTlo, K0P, HID, b[0], pHA);

    // ---- layer 1 ----
    buildBTKernel<<<cdiv(HID * KBIG, 256), 256>>>(W[1], L[1], KBIG, HID, HID);
    agg128Kernel<<<aggBlocks, 256>>>(pHA);
    gemmK<<<gemmBlocks, 256, GEMM_SMEM>>>(pAhi, pAlo, pBThi, pBTlo, KBIG, HID, b[1], pHB);

    // ---- layer 2 ----
    buildBTKernel<<<cdiv(HID * KBIG, 256), 256>>>(W[2], L[2], KBIG, HID, HID);
    agg128Kernel<<<aggBlocks, 256>>>(pHB);
    gemmK<<<gemmBlocks, 256, GEMM_SMEM>>>(pAhi, pAlo, pBThi, pBTlo, KBIG, HID, b[2], pHA);

    // ---- layer 3: dout=64 ----
    buildBTKernel<<<cdiv(OUTD * KBIG, 256), 256>>>(W[3], L[3], KBIG, OUTD, HID);
    agg128Kernel<<<aggBlocks, 256>>>(pHA);
    gemmK<<<gemmBlocks, 256, GEMM_SMEM>>>(pAhi, pAlo, pBThi, pBTlo, KBIG, OUTD, b[3], pHf);

    finalKernel<<<cdiv(NN, 256), 256>>>(Wd, bd);
    outputKernel<<<cdiv(PP, 256), 256>>>(ei, out);
}